// round 13
// baseline (speedup 1.0000x reference)
#include <cuda_runtime.h>
#include <cuda_fp16.h>
#include <cstdint>
#include <math.h>

#define NB   2
#define CIN  256     // deform output channels O (GEMM M); also transconv input channels
#define CMID 128     // transconv output channels
#define H0   64
#define W0   64
#define H    128
#define W    128
#define HP   132     // padded (halo 2 each side)
#define KK   9
#define KC   1152    // KK * CMID
#define NPIX 16384
#define QTOT 32768   // GEMM N total
#define KTC  2304    // transconv class-grouped K total (256+512+512+1024)

// ---------------- device scratch ----------------
__device__ float  g_upP[NB][CMID][HP][HP];   // transposed-conv output, zero halo
__device__ __half g_Wa[CIN][KC];             // deform GEMM A, m-major k-contig, fp16
__device__ __half g_Wc[CMID][KTC];           // transconv GEMM A, class-grouped k
__device__ __half g_xhA[NB * CIN * 65 * 64]; // x fp16, padded (zero row u=64)
__device__ __half g_xhB[NB * CIN * 65 * 64]; // x shifted by +1 in j (zero fill)
__device__ int    g_tiy[NB][KK];
__device__ int    g_tix[NB][KK];
__device__ float  g_twgt[NB][KK][4];

__device__ __forceinline__ uint32_t smem_u32(const void* p) {
    uint32_t a;
    asm("{ .reg .u64 t; cvta.to.shared.u64 t, %1; cvt.u32.u64 %0, t; }" : "=r"(a) : "l"(p));
    return a;
}

#define CP16(sm, gp) \
    asm volatile("cp.async.cg.shared.global [%0], [%1], 16;" :: "r"(sm), "l"(gp) : "memory")
#define CP_COMMIT() asm volatile("cp.async.commit_group;" ::: "memory")
#define CP_WAIT1()  asm volatile("cp.async.wait_group 1;" ::: "memory")
#define CP_WAIT0()  asm volatile("cp.async.wait_group 0;" ::: "memory")

#define LDSM4(R0, R1, R2, R3, a) \
    asm volatile("ldmatrix.sync.aligned.m8n8.x4.shared.b16 {%0,%1,%2,%3}, [%4];" \
                 : "=r"(R0), "=r"(R1), "=r"(R2), "=r"(R3) : "r"(a))
#define LDSM4T(R0, R1, R2, R3, a) \
    asm volatile("ldmatrix.sync.aligned.m8n8.x4.trans.shared.b16 {%0,%1,%2,%3}, [%4];" \
                 : "=r"(R0), "=r"(R1), "=r"(R2), "=r"(R3) : "r"(a))

__device__ __forceinline__ void mma_f16(float* c, const uint32_t* a, const uint32_t* b) {
    asm volatile(
        "mma.sync.aligned.m16n8k16.row.col.f32.f16.f16.f32 "
        "{%0,%1,%2,%3}, {%4,%5,%6,%7}, {%8,%9}, {%0,%1,%2,%3};"
        : "+f"(c[0]), "+f"(c[1]), "+f"(c[2]), "+f"(c[3])
        : "r"(a[0]), "r"(a[1]), "r"(a[2]), "r"(a[3]), "r"(b[0]), "r"(b[1]));
}

// ---------------- merged prep: weights + x fp16 + halo zero + offset net ----------------
// blocks: [0,1152) weights | [1152,2192) xprep | [2192,3232) halo zero | 3232 offsets
__global__ void k_prep(const float* __restrict__ w, const float* __restrict__ x,
                       const float* __restrict__ lat,
                       const float* __restrict__ w1, const float* __restrict__ b1,
                       const float* __restrict__ w2, const float* __restrict__ b2) {
    __shared__ float sh[NB][64];
    __shared__ float soff[NB][18];
    int b = blockIdx.x;
    int t = threadIdx.x;
    if (b < 1152) {
        int e = b * 256 + t;   // < 294912
        {   // deform GEMM A: g_Wa[o][kc] ; kc = k*128 + c
            int o  = e / KC;
            int kc = e - o * KC;
            int c  = kc & 127, k = kc >> 7;
            g_Wa[o][kc] = __float2half_rn(w[(o * CMID + c) * KK + k]);
        }
        {   // transconv GEMM A: g_Wc[co][k], class-grouped
            int co = e / KTC;
            int k  = e - co * KTC;
            int ci, ky, kx;
            if (k < 256)       { ci = k; ky = 1; kx = 1; }
            else if (k < 768)  { int kk = k - 256;  ci = kk >> 1; ky = 1;               kx = (kk & 1) * 2; }
            else if (k < 1280) { int kk = k - 768;  ci = kk >> 1; ky = (kk & 1) * 2;    kx = 1; }
            else               { int kk = k - 1280; ci = kk >> 2; ky = ((kk >> 1) & 1) * 2; kx = (kk & 1) * 2; }
            g_Wc[co][k] = __float2half_rn(w[(ci * CMID + co) * KK + ky * 3 + kx]);
        }
    } else if (b < 2192) {
        int idx = (b - 1152) * 256 + t;   // < 266240
        int chunk = idx & 7;
        int row = idx >> 3;                 // (n*256+ci)*65 + u
        int u = row % 65;
        int nc = row / 65;
        int v0 = chunk * 8;
        __align__(16) __half ha[8];
        __align__(16) __half hb[8];
        if (u < 64) {
            const float* src = x + ((size_t)nc * 64 + u) * 64 + v0;
            #pragma unroll
            for (int p = 0; p < 8; p++) ha[p] = __float2half_rn(src[p]);
            #pragma unroll
            for (int p = 0; p < 8; p++) {
                hb[p] = __float2half_rn(0.f);
                if (v0 + p + 1 < 64) hb[p] = __float2half_rn(src[p + 1]);
            }
        } else {
            #pragma unroll
            for (int p = 0; p < 8; p++) { ha[p] = __float2half_rn(0.f); hb[p] = __float2half_rn(0.f); }
        }
        size_t dst = (size_t)row * 64 + v0;
        *reinterpret_cast<uint4*>(&g_xhA[dst]) = *reinterpret_cast<uint4*>(ha);
        *reinterpret_cast<uint4*>(&g_xhB[dst]) = *reinterpret_cast<uint4*>(hb);
    } else if (b < 3232) {
        // zero the halo of g_upP: 256 planes x 1040 border elems = 266240
        int idx = (b - 2192) * 256 + t;
        int plane = idx / 1040;
        int r = idx - plane * 1040;
        int row, col;
        if (r < 528) {
            int rid = r / 132;
            row = (rid < 2) ? rid : rid + 128;   // 0,1,130,131
            col = r - rid * 132;
        } else {
            int r2 = r - 528;
            row = 2 + (r2 >> 2);
            int cid = r2 & 3;
            col = (cid < 2) ? cid : cid + 128;   // 0,1,130,131
        }
        (&g_upP[0][0][0][0])[((size_t)plane * HP + row) * HP + col] = 0.f;
    } else {
        // offset net + tap precompute (single block)
        if (t < 128) {
            int n = t >> 6, o = t & 63;
            float acc = b1[o];
            for (int i = 0; i < CMID; i++)
                acc += lat[n * CMID + i] * w1[(o * CMID + i) * KK + 4];
            sh[n][o] = fmaxf(acc, 0.f);
        }
        __syncthreads();
        if (t < NB * 18) {
            int nn = t / 18, j = t % 18;
            float a = b2[j];
            for (int q = 0; q < 64; q++)
                a += sh[nn][q] * w2[(j * 64 + q) * KK + 4];
            soff[nn][j] = tanhf(a);
        }
        __syncthreads();
        if (t < NB * KK) {
            int nn = t / KK, k = t % KK;
            float oy = soff[nn][2 * k], ox = soff[nn][2 * k + 1];
            float ay = (float)(k / 3 - 1) + oy;
            float ax = (float)(k % 3 - 1) + ox;
            float fy = floorf(ay), fx = floorf(ax);
            float dy = ay - fy, dx = ax - fx;
            g_tiy[nn][k] = (int)fy;
            g_tix[nn][k] = (int)fx;
            g_twgt[nn][k][0] = (1.f - dy) * (1.f - dx);
            g_twgt[nn][k][1] = (1.f - dy) * dx;
            g_twgt[nn][k][2] = dy * (1.f - dx);
            g_twgt[nn][k][3] = dy * dx;
        }
    }
}

// ---------------- kernel B: transposed conv as 4 parity-class HMMA GEMMs ----------------
// heavy classes first: cls = 3 - (bx>>6)
#define TLDA 40
#define TLDB 136
__global__ __launch_bounds__(256, 2) void k_tc() {
    __shared__ __half As[2][128][TLDA];
    __shared__ __half Bs[2][32][TLDB];

    const int bx = blockIdx.x;
    const int cls = 3 - (bx >> 6), cb = bx & 63;
    const int ry = cls >> 1, rx = cls & 1;
    const int sh = ry + rx, nt = 1 << sh;
    const int n = cb >> 5, u0 = (cb & 31) << 1;
    const int koff = (cls == 0) ? 0 : (cls == 1) ? 256 : (cls == 2) ? 768 : 1280;
    const int nkt = 8 << sh;

    const int t = threadIdx.x, wid = t >> 5, lane = t & 31;
    const int gid = lane >> 2, tig = lane & 3, lr = lane & 7, lm = lane >> 3;
    const int wm = wid >> 2, wn = wid & 3;

    const uint32_t asb = smem_u32(&As[0][0][0]);
    const uint32_t bsb = smem_u32(&Bs[0][0][0]);
    const __half* Wc = &g_Wc[0][0];

    float acc[4][4][4];
    #pragma unroll
    for (int i = 0; i < 4; i++)
        #pragma unroll
        for (int j = 0; j < 4; j++)
            #pragma unroll
            for (int c = 0; c < 4; c++) acc[i][j][c] = 0.f;

    auto stage = [&](int buf, int k0) {
        #pragma unroll
        for (int h = 0; h < 2; h++) {
            int c = t + h * 256;
            int row = c >> 2, u4 = c & 3;
            CP16(asb + buf * (128 * TLDA * 2) + row * (TLDA * 2) + u4 * 16,
                 Wc + (size_t)row * KTC + koff + k0 + u4 * 8);
        }
        #pragma unroll
        for (int h = 0; h < 2; h++) {
            int c = t + h * 256;
            int row = c >> 4, rest = c & 15;
            int du = rest >> 3, vv = (rest & 7) * 8;
            int k = k0 + row;
            int ci = k >> sh, tt = k & (nt - 1);
            int ty = tt >> rx, tx = tt & rx;
            int iof = ry & (ty ^ 1);
            int jof = rx & (tx ^ 1);
            const __half* src = jof ? g_xhB : g_xhA;
            size_t ga = ((size_t)(n * CIN + ci) * 65 + (u0 + du + iof)) * 64 + vv;
            CP16(bsb + buf * (32 * TLDB * 2) + row * (TLDB * 2) + (du * 64 + vv) * 2,
                 src + ga);
        }
    };

    stage(0, 0);
    CP_COMMIT();

    for (int kt = 0; kt < nkt; kt++) {
        const int cur = kt & 1;
        if (kt + 1 < nkt) {
            stage(cur ^ 1, (kt + 1) * 32);
            CP_COMMIT();
            CP_WAIT1();
        } else {
            CP_WAIT0();
        }
        __syncthreads();

        const uint32_t as = asb + cur * (128 * TLDA * 2);
        const uint32_t bs = bsb + cur * (32 * TLDB * 2);

        #pragma unroll
        for (int ks = 0; ks < 2; ks++) {
            uint32_t a[4][4], b[4][2];
            #pragma unroll
            for (int mf = 0; mf < 4; mf++) {
                uint32_t row = wm * 64 + mf * 16 + ((lm & 1) << 3) + lr;
                uint32_t colb = ks * 32 + ((lm >> 1) << 4);
                LDSM4(a[mf][0], a[mf][1], a[mf][2], a[mf][3],
                      as + row * (TLDA * 2) + colb);
            }
            #pragma unroll
            for (int np = 0; np < 2; np++) {
                uint32_t r0, r1, r2, r3;
                uint32_t krow = ks * 16 + ((lm & 1) << 3) + lr;
                uint32_t ncol = wn * 32 + np * 16 + ((lm >> 1) << 3);
                LDSM4T(r0, r1, r2, r3, bs + krow * (TLDB * 2) + ncol * 2);
                b[2 * np][0] = r0;     b[2 * np][1] = r1;
                b[2 * np + 1][0] = r2; b[2 * np + 1][1] = r3;
            }
            #pragma unroll
            for (int mf = 0; mf < 4; mf++)
                #pragma unroll
                for (int nf = 0; nf < 4; nf++)
                    mma_f16(acc[mf][nf], a[mf], b[nf]);
        }
        __syncthreads();
    }

    // epilogue into padded layout: row = Y+2, col = X+2
    #pragma unroll
    for (int mf = 0; mf < 4; mf++) {
        int m = wm * 64 + mf * 16 + gid;
        #pragma unroll
        for (int nf = 0; nf < 4; nf++) {
            int nn = wn * 32 + nf * 8 + tig * 2;
            int du = nn >> 6, v = nn & 63;
            int Y = 2 * (u0 + du) + ry + 2;
            int X = 2 * v + rx + 2;
            g_upP[n][m][Y][X]         = acc[mf][nf][0];
            g_upP[n][m][Y][X + 2]     = acc[mf][nf][1];
            g_upP[n][m + 8][Y][X]     = acc[mf][nf][2];
            g_upP[n][m + 8][Y][X + 2] = acc[mf][nf][3];
        }
    }
}

// ---------------- kernel C: fused sample + fp16 HMMA GEMM ----------------
// B tile (32 kc x 128 q) is bilinear-sampled from g_upP directly into smem.
// All 128 q of a block share one (n, y): n = nb>>7, y = nb&127.
#define BK      32
#define NTILE   36            // 1152 / 32
#define LDH     40
#define LDB     136

__global__ __launch_bounds__(256, 2) void k_gemm(float* __restrict__ out) {
    __shared__ __half As[2][128][LDH];
    __shared__ __half Bs[2][32][LDB];

    const int nb = blockIdx.x;           // 256 N-blocks of 128 q
    const int mb = blockIdx.y;           // 2 M-blocks of 128 o
    const int t  = threadIdx.x;
    const int wid = t >> 5, lane = t & 31;
    const int gid = lane >> 2, tig = lane & 3;
    const int lr = lane & 7, lm = lane >> 3;
    const int wm = wid >> 2, wn = wid & 3;
    const int m0 = mb * 128, n0 = nb * 128;
    const int n = nb >> 7, y = nb & 127;   // image / row of this q-block

    const uint32_t asb = smem_u32(&As[0][0][0]);
    const uint32_t bsb = smem_u32(&Bs[0][0][0]);

    const __half* Ab = &g_Wa[m0][0];

    // per-thread B staging coords: one kc-row, 16 consecutive q
    const int brow = t >> 3;             // 0..31
    const int bq0  = (t & 7) * 16;       // 0..112

    float acc[4][4][4];
    #pragma unroll
    for (int i = 0; i < 4; i++)
        #pragma unroll
        for (int j = 0; j < 4; j++)
            #pragma unroll
            for (int c = 0; c < 4; c++) acc[i][j][c] = 0.f;

    auto stageA = [&](int buf, int k0) {
        #pragma unroll
        for (int h = 0; h < 2; h++) {
            int c = t + h * 256;
            int row = c >> 2, u4 = c & 3;
            CP16(asb + buf * (128 * LDH * 2) + row * (LDH * 2) + u4 * 16,
                 Ab + (size_t)row * KC + k0 + u4 * 8);
        }
    };

    auto stageB = [&](int buf, int k0) {
        int kc = k0 + brow;
        int k = kc >> 7, c = kc & 127;
        int iy = g_tiy[n][k], ix = g_tix[n][k];
        float w00 = g_twgt[n][k][0], w01 = g_twgt[n][k][1];
        float w10 = g_twgt[n][k][2], w11 = g_twgt[n][k][3];
        const float* U = &g_upP[n][c][0][0];
        int base = (y + iy + 2) * HP + (bq0 + ix + 2);

        __align__(16) __half hv[16];
        float a0 = U[base], a1 = U[base + HP];
        #pragma unroll
        for (int p = 0; p < 16; p++) {
            float b0 = U[base + p + 1];
            float b1 = U[base + HP + p + 1];
            hv[p] = __float2half_rn(w00 * a0 + w01 * b0 + w10 * a1 + w11 * b1);
            a0 = b0; a1 = b1;
        }
        __half* dst = &Bs[buf][brow][bq0];
        *reinterpret_cast<uint4*>(dst)     = *reinterpret_cast<uint4*>(hv);
        *reinterpret_cast<uint4*>(dst + 8) = *reinterpret_cast<uint4*>(hv + 8);
    };

    // prologue
    stageA(0, 0);
    CP_COMMIT();
    stageB(0, 0);
    CP_WAIT0();
    __syncthreads();

    for (int kt = 0; kt < NTILE; kt++) {
        const int cur = kt & 1;
        const bool more = (kt + 1 < NTILE);
        if (more) {
            stageA(cur ^ 1, (kt + 1) * BK);
            CP_COMMIT();
            stageB(cur ^ 1, (kt + 1) * BK);
        }

        const uint32_t as = asb + cur * (128 * LDH * 2);
        const uint32_t bs = bsb + cur * (32 * LDB * 2);

        #pragma unroll
        for (int ks = 0; ks < 2; ks++) {
            uint32_t a[4][4], b[4][2];
            #pragma unroll
            for (int mf = 0; mf < 4; mf++) {
                uint32_t row = wm * 64 + mf * 16 + ((lm & 1) << 3) + lr;
                uint32_t colb = ks * 32 + ((lm >> 1) << 4);
                LDSM4(a[mf][0], a[mf][1], a[mf][2], a[mf][3],
                      as + row * (LDH * 2) + colb);
            }
            #pragma unroll
            for (int np = 0; np < 2; np++) {
                uint32_t r0, r1, r2, r3;
                uint32_t krow = ks * 16 + ((lm & 1) << 3) + lr;
                uint32_t ncol = wn * 32 + np * 16 + ((lm >> 1) << 3);
                LDSM4T(r0, r1, r2, r3, bs + krow * (LDB * 2) + ncol * 2);
                b[2 * np][0] = r0;     b[2 * np][1] = r1;
                b[2 * np + 1][0] = r2; b[2 * np + 1][1] = r3;
            }
            #pragma unroll
            for (int mf = 0; mf < 4; mf++)
                #pragma unroll
                for (int nf = 0; nf < 4; nf++)
                    mma_f16(acc[mf][nf], a[mf], b[nf]);
        }

        if (more) CP_WAIT0();
        __syncthreads();
    }

    const int nbat = n0 >> 14;
    const int pix0 = n0 & 16383;
    #pragma unroll
    for (int mf = 0; mf < 4; mf++) {
        int o = m0 + wm * 64 + mf * 16 + gid;
        #pragma unroll
        for (int nf = 0; nf < 4; nf++) {
            int qoff = pix0 + wn * 32 + nf * 8 + tig * 2;
            float* d0 = out + ((size_t)nbat * CIN + o) * NPIX + qoff;
            *reinterpret_cast<float2*>(d0) = make_float2(acc[mf][nf][0], acc[mf][nf][1]);
            float* d1 = out + ((size_t)nbat * CIN + o + 8) * NPIX + qoff;
            *reinterpret_cast<float2*>(d1) = make_float2(acc[mf][nf][2], acc[mf][nf][3]);
        }
    }
}

// ---------------- launch ----------------
extern "C" void kernel_launch(void* const* d_in, const int* in_sizes, int n_in,
                              void* d_out, int out_size) {
    const float* x   = (const float*)d_in[0];   // [2,256,64,64]
    const float* lat = (const float*)d_in[1];   // [2,128,1,1]
    const float* tw  = (const float*)d_in[2];   // [256,128,3,3]
    const float* w1  = (const float*)d_in[3];   // [64,128,3,3]
    const float* b1  = (const float*)d_in[4];   // [64]
    const float* w2  = (const float*)d_in[5];   // [18,64,3,3]
    const float* b2  = (const float*)d_in[6];   // [18]
    float* out = (float*)d_out;                 // [2,256,128,128]

    k_prep<<<3233, 256>>>(tw, x, lat, w1, b1, w2, b2);
    k_tc<<<256, 256>>>();
    k_gemm<<<dim3(256, 2), 256>>>(out);
}

// round 14
// speedup vs baseline: 2.5005x; 2.5005x over previous
#include <cuda_runtime.h>
#include <cuda_fp16.h>
#include <cstdint>
#include <math.h>

#define NB   2
#define CIN  256     // deform output channels O (GEMM M); also transconv input channels
#define CMID 128     // transconv output channels
#define H0   64
#define W0   64
#define H    128
#define W    128
#define KK   9
#define KC   1152    // KK * CMID
#define NPIX 16384
#define QTOT 32768   // GEMM N total
#define KTC  2304    // transconv class-grouped K total (256+512+512+1024)

// ---------------- device scratch ----------------
__device__ float  g_up[NB][CMID][H][W];      // transposed-conv output
__device__ __half g_ST[KC][QTOT];            // im2col, [kc][q] N-contiguous, fp16
__device__ __half g_Wa[CIN][KC];             // deform GEMM A, m-major k-contig, fp16
__device__ __half g_Wc[CMID][KTC];           // transconv GEMM A, class-grouped k
__device__ __half g_xhA[NB * CIN * 65 * 64]; // x fp16, padded (zero row u=64)
__device__ __half g_xhB[NB * CIN * 65 * 64]; // x shifted by +1 in j (zero fill)
__device__ int    g_tiy[NB][KK];
__device__ int    g_tix[NB][KK];
__device__ float  g_twgt[NB][KK][4];

__device__ __forceinline__ uint32_t smem_u32(const void* p) {
    uint32_t a;
    asm("{ .reg .u64 t; cvta.to.shared.u64 t, %1; cvt.u32.u64 %0, t; }" : "=r"(a) : "l"(p));
    return a;
}

#define CP16(sm, gp) \
    asm volatile("cp.async.cg.shared.global [%0], [%1], 16;" :: "r"(sm), "l"(gp) : "memory")
#define CP_COMMIT() asm volatile("cp.async.commit_group;" ::: "memory")
#define CP_WAIT1()  asm volatile("cp.async.wait_group 1;" ::: "memory")
#define CP_WAIT2()  asm volatile("cp.async.wait_group 2;" ::: "memory")
#define CP_WAIT0()  asm volatile("cp.async.wait_group 0;" ::: "memory")

#define LDSM4(R0, R1, R2, R3, a) \
    asm volatile("ldmatrix.sync.aligned.m8n8.x4.shared.b16 {%0,%1,%2,%3}, [%4];" \
                 : "=r"(R0), "=r"(R1), "=r"(R2), "=r"(R3) : "r"(a))
#define LDSM4T(R0, R1, R2, R3, a) \
    asm volatile("ldmatrix.sync.aligned.m8n8.x4.trans.shared.b16 {%0,%1,%2,%3}, [%4];" \
                 : "=r"(R0), "=r"(R1), "=r"(R2), "=r"(R3) : "r"(a))

__device__ __forceinline__ void mma_f16(float* c, const uint32_t* a, const uint32_t* b) {
    asm volatile(
        "mma.sync.aligned.m16n8k16.row.col.f32.f16.f16.f32 "
        "{%0,%1,%2,%3}, {%4,%5,%6,%7}, {%8,%9}, {%0,%1,%2,%3};"
        : "+f"(c[0]), "+f"(c[1]), "+f"(c[2]), "+f"(c[3])
        : "r"(a[0]), "r"(a[1]), "r"(a[2]), "r"(a[3]), "r"(b[0]), "r"(b[1]));
}

// ---------------- merged prep: weights + x fp16 + offset net ----------------
// blocks: [0,1152) weights | [1152,2192) xprep | 2192 offsets
__global__ void k_prep(const float* __restrict__ w, const float* __restrict__ x,
                       const float* __restrict__ lat,
                       const float* __restrict__ w1, const float* __restrict__ b1,
                       const float* __restrict__ w2, const float* __restrict__ b2) {
    __shared__ float sh[NB][64];
    __shared__ float soff[NB][18];
    int b = blockIdx.x;
    int t = threadIdx.x;
    if (b < 1152) {
        int e = b * 256 + t;   // < 294912
        {   // deform GEMM A: g_Wa[o][kc] ; kc = k*128 + c
            int o  = e / KC;
            int kc = e - o * KC;
            int c  = kc & 127, k = kc >> 7;
            g_Wa[o][kc] = __float2half_rn(w[(o * CMID + c) * KK + k]);
        }
        {   // transconv GEMM A: g_Wc[co][k], class-grouped
            int co = e / KTC;
            int k  = e - co * KTC;
            int ci, ky, kx;
            if (k < 256)       { ci = k; ky = 1; kx = 1; }
            else if (k < 768)  { int kk = k - 256;  ci = kk >> 1; ky = 1;               kx = (kk & 1) * 2; }
            else if (k < 1280) { int kk = k - 768;  ci = kk >> 1; ky = (kk & 1) * 2;    kx = 1; }
            else               { int kk = k - 1280; ci = kk >> 2; ky = ((kk >> 1) & 1) * 2; kx = (kk & 1) * 2; }
            g_Wc[co][k] = __float2half_rn(w[(ci * CMID + co) * KK + ky * 3 + kx]);
        }
    } else if (b < 2192) {
        int idx = (b - 1152) * 256 + t;   // < 266240
        int chunk = idx & 7;
        int row = idx >> 3;                 // (n*256+ci)*65 + u
        int u = row % 65;
        int nc = row / 65;
        int v0 = chunk * 8;
        __align__(16) __half ha[8];
        __align__(16) __half hb[8];
        if (u < 64) {
            const float* src = x + ((size_t)nc * 64 + u) * 64 + v0;
            #pragma unroll
            for (int p = 0; p < 8; p++) ha[p] = __float2half_rn(src[p]);
            #pragma unroll
            for (int p = 0; p < 8; p++) {
                hb[p] = __float2half_rn(0.f);
                if (v0 + p + 1 < 64) hb[p] = __float2half_rn(src[p + 1]);
            }
        } else {
            #pragma unroll
            for (int p = 0; p < 8; p++) { ha[p] = __float2half_rn(0.f); hb[p] = __float2half_rn(0.f); }
        }
        size_t dst = (size_t)row * 64 + v0;
        *reinterpret_cast<uint4*>(&g_xhA[dst]) = *reinterpret_cast<uint4*>(ha);
        *reinterpret_cast<uint4*>(&g_xhB[dst]) = *reinterpret_cast<uint4*>(hb);
    } else {
        // offset net + tap precompute (single block)
        if (t < 128) {
            int n = t >> 6, o = t & 63;
            float acc = b1[o];
            for (int i = 0; i < CMID; i++)
                acc += lat[n * CMID + i] * w1[(o * CMID + i) * KK + 4];
            sh[n][o] = fmaxf(acc, 0.f);
        }
        __syncthreads();
        if (t < NB * 18) {
            int nn = t / 18, j = t % 18;
            float a = b2[j];
            for (int q = 0; q < 64; q++)
                a += sh[nn][q] * w2[(j * 64 + q) * KK + 4];
            soff[nn][j] = tanhf(a);
        }
        __syncthreads();
        if (t < NB * KK) {
            int nn = t / KK, k = t % KK;
            float oy = soff[nn][2 * k], ox = soff[nn][2 * k + 1];
            float ay = (float)(k / 3 - 1) + oy;
            float ax = (float)(k % 3 - 1) + ox;
            float fy = floorf(ay), fx = floorf(ax);
            float dy = ay - fy, dx = ax - fx;
            g_tiy[nn][k] = (int)fy;
            g_tix[nn][k] = (int)fx;
            g_twgt[nn][k][0] = (1.f - dy) * (1.f - dx);
            g_twgt[nn][k][1] = (1.f - dy) * dx;
            g_twgt[nn][k][2] = dy * (1.f - dx);
            g_twgt[nn][k][3] = dy * dx;
        }
    }
}

// ---------------- kernel B: transposed conv as 4 parity-class HMMA GEMMs ----------------
// heavy classes first: cls = 3 - (bx>>6)
#define TLDA 40
#define TLDB 136
__global__ __launch_bounds__(256, 2) void k_tc() {
    __shared__ __half As[2][128][TLDA];
    __shared__ __half Bs[2][32][TLDB];

    const int bx = blockIdx.x;
    const int cls = 3 - (bx >> 6), cb = bx & 63;
    const int ry = cls >> 1, rx = cls & 1;
    const int sh = ry + rx, nt = 1 << sh;
    const int n = cb >> 5, u0 = (cb & 31) << 1;
    const int koff = (cls == 0) ? 0 : (cls == 1) ? 256 : (cls == 2) ? 768 : 1280;
    const int nkt = 8 << sh;

    const int t = threadIdx.x, wid = t >> 5, lane = t & 31;
    const int gid = lane >> 2, tig = lane & 3, lr = lane & 7, lm = lane >> 3;
    const int wm = wid >> 2, wn = wid & 3;

    const uint32_t asb = smem_u32(&As[0][0][0]);
    const uint32_t bsb = smem_u32(&Bs[0][0][0]);
    const __half* Wc = &g_Wc[0][0];

    float acc[4][4][4];
    #pragma unroll
    for (int i = 0; i < 4; i++)
        #pragma unroll
        for (int j = 0; j < 4; j++)
            #pragma unroll
            for (int c = 0; c < 4; c++) acc[i][j][c] = 0.f;

    auto stage = [&](int buf, int k0) {
        #pragma unroll
        for (int h = 0; h < 2; h++) {
            int c = t + h * 256;
            int row = c >> 2, u4 = c & 3;
            CP16(asb + buf * (128 * TLDA * 2) + row * (TLDA * 2) + u4 * 16,
                 Wc + (size_t)row * KTC + koff + k0 + u4 * 8);
        }
        #pragma unroll
        for (int h = 0; h < 2; h++) {
            int c = t + h * 256;
            int row = c >> 4, rest = c & 15;
            int du = rest >> 3, vv = (rest & 7) * 8;
            int k = k0 + row;
            int ci = k >> sh, tt = k & (nt - 1);
            int ty = tt >> rx, tx = tt & rx;
            int iof = ry & (ty ^ 1);
            int jof = rx & (tx ^ 1);
            const __half* src = jof ? g_xhB : g_xhA;
            size_t ga = ((size_t)(n * CIN + ci) * 65 + (u0 + du + iof)) * 64 + vv;
            CP16(bsb + buf * (32 * TLDB * 2) + row * (TLDB * 2) + (du * 64 + vv) * 2,
                 src + ga);
        }
    };

    stage(0, 0);
    CP_COMMIT();

    for (int kt = 0; kt < nkt; kt++) {
        const int cur = kt & 1;
        if (kt + 1 < nkt) {
            stage(cur ^ 1, (kt + 1) * 32);
            CP_COMMIT();
            CP_WAIT1();
        } else {
            CP_WAIT0();
        }
        __syncthreads();

        const uint32_t as = asb + cur * (128 * TLDA * 2);
        const uint32_t bs = bsb + cur * (32 * TLDB * 2);

        #pragma unroll
        for (int ks = 0; ks < 2; ks++) {
            uint32_t a[4][4], b[4][2];
            #pragma unroll
            for (int mf = 0; mf < 4; mf++) {
                uint32_t row = wm * 64 + mf * 16 + ((lm & 1) << 3) + lr;
                uint32_t colb = ks * 32 + ((lm >> 1) << 4);
                LDSM4(a[mf][0], a[mf][1], a[mf][2], a[mf][3],
                      as + row * (TLDA * 2) + colb);
            }
            #pragma unroll
            for (int np = 0; np < 2; np++) {
                uint32_t r0, r1, r2, r3;
                uint32_t krow = ks * 16 + ((lm & 1) << 3) + lr;
                uint32_t ncol = wn * 32 + np * 16 + ((lm >> 1) << 3);
                LDSM4T(r0, r1, r2, r3, bs + krow * (TLDB * 2) + ncol * 2);
                b[2 * np][0] = r0;     b[2 * np][1] = r1;
                b[2 * np + 1][0] = r2; b[2 * np + 1][1] = r3;
            }
            #pragma unroll
            for (int mf = 0; mf < 4; mf++)
                #pragma unroll
                for (int nf = 0; nf < 4; nf++)
                    mma_f16(acc[mf][nf], a[mf], b[nf]);
        }
        __syncthreads();
    }

    #pragma unroll
    for (int mf = 0; mf < 4; mf++) {
        int m = wm * 64 + mf * 16 + gid;
        #pragma unroll
        for (int nf = 0; nf < 4; nf++) {
            int nn = wn * 32 + nf * 8 + tig * 2;
            int du = nn >> 6, v = nn & 63;
            int Y = 2 * (u0 + du) + ry;
            int X = 2 * v + rx;
            g_up[n][m][Y][X]         = acc[mf][nf][0];
            g_up[n][m][Y][X + 2]     = acc[mf][nf][1];
            g_up[n][m + 8][Y][X]     = acc[mf][nf][2];
            g_up[n][m + 8][Y][X + 2] = acc[mf][nf][3];
        }
    }
}

// ---------------- kernel C1: bilinear gather -> [kc][q] fp16 (4 q/thread, predicated) ----------------
__global__ __launch_bounds__(256) void k_sample() {
    int idx = blockIdx.x * 256 + threadIdx.x;   // 9,437,184 threads, 4 q each
    int e = idx << 2;
    int x0 = e & 127;
    int y  = (e >> 7) & 127;
    int n  = (e >> 14) & 1;
    int kc = e >> 15;                  // 0..1151
    int c  = kc & 127, k = kc >> 7;

    int iy = g_tiy[n][k], ix = g_tix[n][k];
    float w00 = g_twgt[n][k][0], w01 = g_twgt[n][k][1];
    float w10 = g_twgt[n][k][2], w11 = g_twgt[n][k][3];

    const float* U = &g_up[n][c][0][0];
    int r0 = y + iy, r1 = r0 + 1;
    bool v0 = (r0 >= 0) && (r0 < H);
    bool v1 = (r1 >= 0) && (r1 < H);
    int cb = x0 + ix;

    float row0[5], row1[5];
    #pragma unroll
    for (int u = 0; u < 5; u++) {
        int col = cb + u;
        bool vc = (col >= 0) && (col < W);
        row0[u] = (v0 && vc) ? U[r0 * W + col] : 0.f;
        row1[u] = (v1 && vc) ? U[r1 * W + col] : 0.f;
    }
    __half2 p0, p1;
    p0.x = __float2half_rn(w00 * row0[0] + w01 * row0[1] + w10 * row1[0] + w11 * row1[1]);
    p0.y = __float2half_rn(w00 * row0[1] + w01 * row0[2] + w10 * row1[1] + w11 * row1[2]);
    p1.x = __float2half_rn(w00 * row0[2] + w01 * row0[3] + w10 * row1[2] + w11 * row1[3]);
    p1.y = __float2half_rn(w00 * row0[3] + w01 * row0[4] + w10 * row1[3] + w11 * row1[4]);

    int q0 = (n << 14) + (y << 7) + x0;
    __half2* dst = reinterpret_cast<__half2*>(&g_ST[kc][q0]);
    dst[0] = p0;
    dst[1] = p1;
}

// ---------------- kernel C2: fp16 HMMA GEMM, 3-stage pipeline, 128x128 tiles ----------------
#define BK      32
#define NTILE   36            // 1152 / 32
#define LDH     40
#define LDB     136
#define ASTG    (128 * LDH * 2)   // 10240 B per A stage
#define BSTG    (32 * LDB * 2)    // 8704 B per B stage
#define GSMEM   (3 * (ASTG + BSTG))  // 56832 B

__global__ __launch_bounds__(256, 2) void k_gemm(float* __restrict__ out) {
    extern __shared__ char dsm[];

    const int nb = blockIdx.x;           // 256 N-blocks of 128 q
    const int mb = blockIdx.y;           // 2 M-blocks of 128 o
    const int t  = threadIdx.x;
    const int wid = t >> 5, lane = t & 31;
    const int gid = lane >> 2, tig = lane & 3;
    const int lr = lane & 7, lm = lane >> 3;
    const int wm = wid >> 2, wn = wid & 3;
    const int m0 = mb * 128, n0 = nb * 128;

    const uint32_t smb = smem_u32(dsm);
    uint32_t sA0 = smb,              sB0 = smb + 3 * ASTG;
    uint32_t sA1 = smb + ASTG,       sB1 = sB0 + BSTG;
    uint32_t sA2 = smb + 2 * ASTG,   sB2 = sB0 + 2 * BSTG;

    const __half* Ab = &g_Wa[m0][0];
    const __half* Bg = &g_ST[0][0];

    float acc[4][4][4];
    #pragma unroll
    for (int i = 0; i < 4; i++)
        #pragma unroll
        for (int j = 0; j < 4; j++)
            #pragma unroll
            for (int c = 0; c < 4; c++) acc[i][j][c] = 0.f;

    auto stage = [&](uint32_t ab, uint32_t bb, int k0) {
        // A: 128 rows x 32 k = 512 x 16B
        #pragma unroll
        for (int h = 0; h < 2; h++) {
            int c = t + h * 256;
            int row = c >> 2, u4 = c & 3;
            CP16(ab + row * (LDH * 2) + u4 * 16, Ab + (size_t)row * KC + k0 + u4 * 8);
        }
        // B: 32 k-rows x 128 q = 512 x 16B
        #pragma unroll
        for (int h = 0; h < 2; h++) {
            int c = t + h * 256;
            int row = c >> 4, vv = (c & 15) * 8;
            CP16(bb + row * (LDB * 2) + vv * 2, Bg + (size_t)(k0 + row) * QTOT + n0 + vv);
        }
    };

    stage(sA0, sB0, 0);
    CP_COMMIT();
    stage(sA1, sB1, BK);
    CP_COMMIT();

    for (int kt = 0; kt < NTILE; kt++) {
        if (kt + 2 < NTILE) stage(sA2, sB2, (kt + 2) * BK);
        CP_COMMIT();
        CP_WAIT2();
        __syncthreads();

        const uint32_t as = sA0, bs = sB0;

        #pragma unroll
        for (int ks = 0; ks < 2; ks++) {
            uint32_t a[4][4], b[4][2];
            #pragma unroll
            for (int mf = 0; mf < 4; mf++) {
                uint32_t row = wm * 64 + mf * 16 + ((lm & 1) << 3) + lr;
                uint32_t colb = ks * 32 + ((lm >> 1) << 4);
                LDSM4(a[mf][0], a[mf][1], a[mf][2], a[mf][3],
                      as + row * (LDH * 2) + colb);
            }
            #pragma unroll
            for (int np = 0; np < 2; np++) {
                uint32_t r0, r1, r2, r3;
                uint32_t krow = ks * 16 + ((lm & 1) << 3) + lr;
                uint32_t ncol = wn * 32 + np * 16 + ((lm >> 1) << 3);
                LDSM4T(r0, r1, r2, r3, bs + krow * (LDB * 2) + ncol * 2);
                b[2 * np][0] = r0;     b[2 * np][1] = r1;
                b[2 * np + 1][0] = r2; b[2 * np + 1][1] = r3;
            }
            #pragma unroll
            for (int mf = 0; mf < 4; mf++)
                #pragma unroll
                for (int nf = 0; nf < 4; nf++)
                    mma_f16(acc[mf][nf], a[mf], b[nf]);
        }
        __syncthreads();

        // rotate buffers
        uint32_t ta = sA0; sA0 = sA1; sA1 = sA2; sA2 = ta;
        uint32_t tb = sB0; sB0 = sB1; sB1 = sB2; sB2 = tb;
    }

    const int nbat = n0 >> 14;
    const int pix0 = n0 & 16383;
    #pragma unroll
    for (int mf = 0; mf < 4; mf++) {
        int o = m0 + wm * 64 + mf * 16 + gid;
        #pragma unroll
        for (int nf = 0; nf < 4; nf++) {
            int qoff = pix0 + wn * 32 + nf * 8 + tig * 2;
            float* d0 = out + ((size_t)nbat * CIN + o) * NPIX + qoff;
            *reinterpret_cast<float2*>(d0) = make_float2(acc[mf][nf][0], acc[mf][nf][1]);
            float* d1 = out + ((size_t)nbat * CIN + o + 8) * NPIX + qoff;
            *reinterpret_cast<float2*>(d1) = make_float2(acc[mf][nf][2], acc[mf][nf][3]);
        }
    }
}

// ---------------- launch ----------------
extern "C" void kernel_launch(void* const* d_in, const int* in_sizes, int n_in,
                              void* d_out, int out_size) {
    const float* x   = (const float*)d_in[0];   // [2,256,64,64]
    const float* lat = (const float*)d_in[1];   // [2,128,1,1]
    const float* tw  = (const float*)d_in[2];   // [256,128,3,3]
    const float* w1  = (const float*)d_in[3];   // [64,128,3,3]
    const float* b1  = (const float*)d_in[4];   // [64]
    const float* w2  = (const float*)d_in[5];   // [18,64,3,3]
    const float* b2  = (const float*)d_in[6];   // [18]
    float* out = (float*)d_out;                 // [2,256,128,128]

    cudaFuncSetAttribute(k_gemm, cudaFuncAttributeMaxDynamicSharedMemorySize, GSMEM);

    k_prep<<<2193, 256>>>(tw, x, lat, w1, b1, w2, b2);
    k_tc<<<256, 256>>>();
    k_sample<<<36864, 256>>>();
    k_gemm<<<dim3(256, 2), 256, GSMEM>>>(out);
}

// round 16
// speedup vs baseline: 2.5832x; 1.0331x over previous
#include <cuda_runtime.h>
#include <cuda_fp16.h>
#include <cstdint>
#include <math.h>

#define NB   2
#define CIN  256     // deform output channels O (GEMM M); also transconv input channels
#define CMID 128     // transconv output channels
#define H0   64
#define W0   64
#define H    128
#define W    128
#define KK   9
#define KC   1152    // KK * CMID
#define NPIX 16384
#define QTOT 32768   // GEMM N total
#define KTC  2304    // transconv class-grouped K total (256+512+512+1024)

// ---------------- device scratch ----------------
__device__ float  g_up[NB][CMID][H][W];      // transposed-conv output
__device__ __half g_ST[KC][QTOT];            // im2col, [kc][q] N-contiguous, fp16
__device__ __half g_Wa[CIN][KC];             // deform GEMM A, m-major k-contig, fp16
__device__ __half g_Wc[CMID][KTC];           // transconv GEMM A, class-grouped k
__device__ __half g_xhA[NB * CIN * 65 * 64]; // x fp16, padded (zero row u=64)
__device__ __half g_xhB[NB * CIN * 65 * 64]; // x shifted by +1 in j (zero fill)
__device__ int    g_tiy[NB][KK];
__device__ int    g_tix[NB][KK];
__device__ float  g_twgt[NB][KK][4];

__device__ __forceinline__ uint32_t smem_u32(const void* p) {
    uint32_t a;
    asm("{ .reg .u64 t; cvta.to.shared.u64 t, %1; cvt.u32.u64 %0, t; }" : "=r"(a) : "l"(p));
    return a;
}

#define CP16(sm, gp) \
    asm volatile("cp.async.cg.shared.global [%0], [%1], 16;" :: "r"(sm), "l"(gp) : "memory")
#define CP_COMMIT() asm volatile("cp.async.commit_group;" ::: "memory")
#define CP_WAIT1()  asm volatile("cp.async.wait_group 1;" ::: "memory")
#define CP_WAIT2()  asm volatile("cp.async.wait_group 2;" ::: "memory")
#define CP_WAIT0()  asm volatile("cp.async.wait_group 0;" ::: "memory")

#define LDSM4(R0, R1, R2, R3, a) \
    asm volatile("ldmatrix.sync.aligned.m8n8.x4.shared.b16 {%0,%1,%2,%3}, [%4];" \
                 : "=r"(R0), "=r"(R1), "=r"(R2), "=r"(R3) : "r"(a))
#define LDSM4T(R0, R1, R2, R3, a) \
    asm volatile("ldmatrix.sync.aligned.m8n8.x4.trans.shared.b16 {%0,%1,%2,%3}, [%4];" \
                 : "=r"(R0), "=r"(R1), "=r"(R2), "=r"(R3) : "r"(a))

__device__ __forceinline__ void mma_f16(float* c, const uint32_t* a, const uint32_t* b) {
    asm volatile(
        "mma.sync.aligned.m16n8k16.row.col.f32.f16.f16.f32 "
        "{%0,%1,%2,%3}, {%4,%5,%6,%7}, {%8,%9}, {%0,%1,%2,%3};"
        : "+f"(c[0]), "+f"(c[1]), "+f"(c[2]), "+f"(c[3])
        : "r"(a[0]), "r"(a[1]), "r"(a[2]), "r"(a[3]), "r"(b[0]), "r"(b[1]));
}

// ---------------- merged prep: weights + x fp16 + offset net ----------------
// blocks: [0,1152) weights | [1152,2192) xprep | 2192 offsets
__global__ void k_prep(const float* __restrict__ w, const float* __restrict__ x,
                       const float* __restrict__ lat,
                       const float* __restrict__ w1, const float* __restrict__ b1,
                       const float* __restrict__ w2, const float* __restrict__ b2) {
    __shared__ float sh[NB][64];
    __shared__ float soff[NB][18];
    int b = blockIdx.x;
    int t = threadIdx.x;
    if (b < 1152) {
        int e = b * 256 + t;   // < 294912
        {   // deform GEMM A: g_Wa[o][kc] ; kc = k*128 + c
            int o  = e / KC;
            int kc = e - o * KC;
            int c  = kc & 127, k = kc >> 7;
            g_Wa[o][kc] = __float2half_rn(w[(o * CMID + c) * KK + k]);
        }
        {   // transconv GEMM A: g_Wc[co][k], class-grouped
            int co = e / KTC;
            int k  = e - co * KTC;
            int ci, ky, kx;
            if (k < 256)       { ci = k; ky = 1; kx = 1; }
            else if (k < 768)  { int kk = k - 256;  ci = kk >> 1; ky = 1;               kx = (kk & 1) * 2; }
            else if (k < 1280) { int kk = k - 768;  ci = kk >> 1; ky = (kk & 1) * 2;    kx = 1; }
            else               { int kk = k - 1280; ci = kk >> 2; ky = ((kk >> 1) & 1) * 2; kx = (kk & 1) * 2; }
            g_Wc[co][k] = __float2half_rn(w[(ci * CMID + co) * KK + ky * 3 + kx]);
        }
    } else if (b < 2192) {
        int idx = (b - 1152) * 256 + t;   // < 266240
        int chunk = idx & 7;
        int row = idx >> 3;                 // (n*256+ci)*65 + u
        int u = row % 65;
        int nc = row / 65;
        int v0 = chunk * 8;
        __align__(16) __half ha[8];
        __align__(16) __half hb[8];
        if (u < 64) {
            const float* src = x + ((size_t)nc * 64 + u) * 64 + v0;
            #pragma unroll
            for (int p = 0; p < 8; p++) ha[p] = __float2half_rn(src[p]);
            #pragma unroll
            for (int p = 0; p < 8; p++) {
                hb[p] = __float2half_rn(0.f);
                if (v0 + p + 1 < 64) hb[p] = __float2half_rn(src[p + 1]);
            }
        } else {
            #pragma unroll
            for (int p = 0; p < 8; p++) { ha[p] = __float2half_rn(0.f); hb[p] = __float2half_rn(0.f); }
        }
        size_t dst = (size_t)row * 64 + v0;
        *reinterpret_cast<uint4*>(&g_xhA[dst]) = *reinterpret_cast<uint4*>(ha);
        *reinterpret_cast<uint4*>(&g_xhB[dst]) = *reinterpret_cast<uint4*>(hb);
    } else {
        // offset net + tap precompute (single block)
        if (t < 128) {
            int n = t >> 6, o = t & 63;
            float acc = b1[o];
            for (int i = 0; i < CMID; i++)
                acc += lat[n * CMID + i] * w1[(o * CMID + i) * KK + 4];
            sh[n][o] = fmaxf(acc, 0.f);
        }
        __syncthreads();
        if (t < NB * 18) {
            int nn = t / 18, j = t % 18;
            float a = b2[j];
            for (int q = 0; q < 64; q++)
                a += sh[nn][q] * w2[(j * 64 + q) * KK + 4];
            soff[nn][j] = tanhf(a);
        }
        __syncthreads();
        if (t < NB * KK) {
            int nn = t / KK, k = t % KK;
            float oy = soff[nn][2 * k], ox = soff[nn][2 * k + 1];
            float ay = (float)(k / 3 - 1) + oy;
            float ax = (float)(k % 3 - 1) + ox;
            float fy = floorf(ay), fx = floorf(ax);
            float dy = ay - fy, dx = ax - fx;
            g_tiy[nn][k] = (int)fy;
            g_tix[nn][k] = (int)fx;
            g_twgt[nn][k][0] = (1.f - dy) * (1.f - dx);
            g_twgt[nn][k][1] = (1.f - dy) * dx;
            g_twgt[nn][k][2] = dy * (1.f - dx);
            g_twgt[nn][k][3] = dy * dx;
        }
    }
}

// ---------------- kernel B: transposed conv as 4 parity-class HMMA GEMMs ----------------
// heavy classes first: cls = 3 - (bx>>6)
#define TLDA 40
#define TLDB 136
__global__ __launch_bounds__(256, 2) void k_tc() {
    __shared__ __half As[2][128][TLDA];
    __shared__ __half Bs[2][32][TLDB];

    const int bx = blockIdx.x;
    const int cls = 3 - (bx >> 6), cb = bx & 63;
    const int ry = cls >> 1, rx = cls & 1;
    const int sh = ry + rx, nt = 1 << sh;
    const int n = cb >> 5, u0 = (cb & 31) << 1;
    const int koff = (cls == 0) ? 0 : (cls == 1) ? 256 : (cls == 2) ? 768 : 1280;
    const int nkt = 8 << sh;

    const int t = threadIdx.x, wid = t >> 5, lane = t & 31;
    const int gid = lane >> 2, tig = lane & 3, lr = lane & 7, lm = lane >> 3;
    const int wm = wid >> 2, wn = wid & 3;

    const uint32_t asb = smem_u32(&As[0][0][0]);
    const uint32_t bsb = smem_u32(&Bs[0][0][0]);
    const __half* Wc = &g_Wc[0][0];

    float acc[4][4][4];
    #pragma unroll
    for (int i = 0; i < 4; i++)
        #pragma unroll
        for (int j = 0; j < 4; j++)
            #pragma unroll
            for (int c = 0; c < 4; c++) acc[i][j][c] = 0.f;

    auto stage = [&](int buf, int k0) {
        #pragma unroll
        for (int h = 0; h < 2; h++) {
            int c = t + h * 256;
            int row = c >> 2, u4 = c & 3;
            CP16(asb + buf * (128 * TLDA * 2) + row * (TLDA * 2) + u4 * 16,
                 Wc + (size_t)row * KTC + koff + k0 + u4 * 8);
        }
        #pragma unroll
        for (int h = 0; h < 2; h++) {
            int c = t + h * 256;
            int row = c >> 4, rest = c & 15;
            int du = rest >> 3, vv = (rest & 7) * 8;
            int k = k0 + row;
            int ci = k >> sh, tt = k & (nt - 1);
            int ty = tt >> rx, tx = tt & rx;
            int iof = ry & (ty ^ 1);
            int jof = rx & (tx ^ 1);
            const __half* src = jof ? g_xhB : g_xhA;
            size_t ga = ((size_t)(n * CIN + ci) * 65 + (u0 + du + iof)) * 64 + vv;
            CP16(bsb + buf * (32 * TLDB * 2) + row * (TLDB * 2) + (du * 64 + vv) * 2,
                 src + ga);
        }
    };

    stage(0, 0);
    CP_COMMIT();

    for (int kt = 0; kt < nkt; kt++) {
        const int cur = kt & 1;
        if (kt + 1 < nkt) {
            stage(cur ^ 1, (kt + 1) * 32);
            CP_COMMIT();
            CP_WAIT1();
        } else {
            CP_WAIT0();
        }
        __syncthreads();

        const uint32_t as = asb + cur * (128 * TLDA * 2);
        const uint32_t bs = bsb + cur * (32 * TLDB * 2);

        #pragma unroll
        for (int ks = 0; ks < 2; ks++) {
            uint32_t a[4][4], b[4][2];
            #pragma unroll
            for (int mf = 0; mf < 4; mf++) {
                uint32_t row = wm * 64 + mf * 16 + ((lm & 1) << 3) + lr;
                uint32_t colb = ks * 32 + ((lm >> 1) << 4);
                LDSM4(a[mf][0], a[mf][1], a[mf][2], a[mf][3],
                      as + row * (TLDA * 2) + colb);
            }
            #pragma unroll
            for (int np = 0; np < 2; np++) {
                uint32_t r0, r1, r2, r3;
                uint32_t krow = ks * 16 + ((lm & 1) << 3) + lr;
                uint32_t ncol = wn * 32 + np * 16 + ((lm >> 1) << 3);
                LDSM4T(r0, r1, r2, r3, bs + krow * (TLDB * 2) + ncol * 2);
                b[2 * np][0] = r0;     b[2 * np][1] = r1;
                b[2 * np + 1][0] = r2; b[2 * np + 1][1] = r3;
            }
            #pragma unroll
            for (int mf = 0; mf < 4; mf++)
                #pragma unroll
                for (int nf = 0; nf < 4; nf++)
                    mma_f16(acc[mf][nf], a[mf], b[nf]);
        }
        __syncthreads();
    }

    #pragma unroll
    for (int mf = 0; mf < 4; mf++) {
        int m = wm * 64 + mf * 16 + gid;
        #pragma unroll
        for (int nf = 0; nf < 4; nf++) {
            int nn = wn * 32 + nf * 8 + tig * 2;
            int du = nn >> 6, v = nn & 63;
            int Y = 2 * (u0 + du) + ry;
            int X = 2 * v + rx;
            g_up[n][m][Y][X]         = acc[mf][nf][0];
            g_up[n][m][Y][X + 2]     = acc[mf][nf][1];
            g_up[n][m + 8][Y][X]     = acc[mf][nf][2];
            g_up[n][m + 8][Y][X + 2] = acc[mf][nf][3];
        }
    }
}

// ---------------- kernel C1: smem-staged bilinear gather -> [kc][q] fp16 ----------------
// one block per (n, c, y): stage up rows y-2..y+2 (cols -2..129) in smem,
// then compute all 9 taps x 128 x from shared memory.
__global__ __launch_bounds__(256) void k_sample() {
    __shared__ float s[5][132];
    __shared__ int   stiy[KK];
    __shared__ int   stix[KK];
    __shared__ float swt[KK][4];

    const int bx = blockIdx.x;        // n*16384 + c*128 + y
    const int y = bx & 127;
    const int c = (bx >> 7) & 127;
    const int n = bx >> 14;
    const int t = threadIdx.x;

    if (t < KK) {
        stiy[t] = g_tiy[n][t];
        stix[t] = g_tix[n][t];
        swt[t][0] = g_twgt[n][t][0];
        swt[t][1] = g_twgt[n][t][1];
        swt[t][2] = g_twgt[n][t][2];
        swt[t][3] = g_twgt[n][t][3];
    }

    // stage 5 rows x 132 cols (row r = y-2+j, col cc = -2..129), zero out-of-range
    const float* U = &g_up[n][c][0][0];
    #pragma unroll
    for (int it = 0; it < 3; it++) {
        int e = t + it * 256;
        if (e < 660) {
            int j  = e / 132;
            int ei = e - j * 132;
            int r  = y - 2 + j;
            int cc = ei - 2;
            float v = 0.f;
            if (r >= 0 && r < H && cc >= 0 && cc < W) v = U[r * W + cc];
            s[j][ei] = v;
        }
    }
    __syncthreads();

    // 9 taps x 64 x-pairs = 576 half2 outputs
    __half* STbase = &g_ST[c][(n << 14) + (y << 7)];   // g_ST[k*128+c] = +k*128*QTOT halves
    #pragma unroll
    for (int it = 0; it < 3; it++) {
        int e = t + it * 256;
        if (e < 576) {
            int k  = e >> 6;          // 0..8
            int xp = e & 63;
            int x  = xp << 1;
            int j0 = stiy[k] + 2;     // 0..3
            int xi = x + stix[k] + 2; // 0..130
            float w00 = swt[k][0], w01 = swt[k][1], w10 = swt[k][2], w11 = swt[k][3];
            float a0 = s[j0][xi], a1 = s[j0][xi + 1], a2 = s[j0][xi + 2];
            float b0 = s[j0 + 1][xi], b1 = s[j0 + 1][xi + 1], b2 = s[j0 + 1][xi + 2];
            __half2 h;
            h.x = __float2half_rn(w00 * a0 + w01 * a1 + w10 * b0 + w11 * b1);
            h.y = __float2half_rn(w00 * a1 + w01 * a2 + w10 * b1 + w11 * b2);
            *reinterpret_cast<__half2*>(STbase + (size_t)k * 128 * QTOT + x) = h;
        }
    }
}

// ---------------- kernel C2: fp16 HMMA GEMM, 3-stage pipeline, 128x128 tiles ----------------
#define BK      32
#define NTILE   36            // 1152 / 32
#define LDH     40
#define LDB     136
#define ASTG    (128 * LDH * 2)   // 10240 B per A stage
#define BSTG    (32 * LDB * 2)    // 8704 B per B stage
#define GSMEM   (3 * (ASTG + BSTG))  // 56832 B

__global__ __launch_bounds__(256, 2) void k_gemm(float* __restrict__ out) {
    extern __shared__ char dsm[];

    const int nb = blockIdx.x;           // 256 N-blocks of 128 q
    const int mb = blockIdx.y;           // 2 M-blocks of 128 o
    const int t  = threadIdx.x;
    const int wid = t >> 5, lane = t & 31;
    const int gid = lane >> 2, tig = lane & 3;
    const int lr = lane & 7, lm = lane >> 3;
    const int wm = wid >> 2, wn = wid & 3;
    const int m0 = mb * 128, n0 = nb * 128;

    const uint32_t smb = smem_u32(dsm);
    uint32_t sA0 = smb,              sB0 = smb + 3 * ASTG;
    uint32_t sA1 = smb + ASTG,       sB1 = sB0 + BSTG;
    uint32_t sA2 = smb + 2 * ASTG,   sB2 = sB0 + 2 * BSTG;

    const __half* Ab = &g_Wa[m0][0];
    const __half* Bg = &g_ST[0][0];

    float acc[4][4][4];
    #pragma unroll
    for (int i = 0; i < 4; i++)
        #pragma unroll
        for (int j = 0; j < 4; j++)
            #pragma unroll
            for (int c = 0; c < 4; c++) acc[i][j][c] = 0.f;

    auto stage = [&](uint32_t ab, uint32_t bb, int k0) {
        // A: 128 rows x 32 k = 512 x 16B
        #pragma unroll
        for (int h = 0; h < 2; h++) {
            int c = t + h * 256;
            int row = c >> 2, u4 = c & 3;
            CP16(ab + row * (LDH * 2) + u4 * 16, Ab + (size_t)row * KC + k0 + u4 * 8);
        }
        // B: 32 k-rows x 128 q = 512 x 16B
        #pragma unroll
        for (int h = 0; h < 2; h++) {
            int c = t + h * 256;
            int row = c >> 4, vv = (c & 15) * 8;
            CP16(bb + row * (LDB * 2) + vv * 2, Bg + (size_t)(k0 + row) * QTOT + n0 + vv);
        }
    };

    stage(sA0, sB0, 0);
    CP_COMMIT();
    stage(sA1, sB1, BK);
    CP_COMMIT();

    for (int kt = 0; kt < NTILE; kt++) {
        if (kt + 2 < NTILE) stage(sA2, sB2, (kt + 2) * BK);
        CP_COMMIT();
        CP_WAIT2();
        __syncthreads();

        const uint32_t as = sA0, bs = sB0;

        #pragma unroll
        for (int ks = 0; ks < 2; ks++) {
            uint32_t a[4][4], b[4][2];
            #pragma unroll
            for (int mf = 0; mf < 4; mf++) {
                uint32_t row = wm * 64 + mf * 16 + ((lm & 1) << 3) + lr;
                uint32_t colb = ks * 32 + ((lm >> 1) << 4);
                LDSM4(a[mf][0], a[mf][1], a[mf][2], a[mf][3],
                      as + row * (LDH * 2) + colb);
            }
            #pragma unroll
            for (int np = 0; np < 2; np++) {
                uint32_t r0, r1, r2, r3;
                uint32_t krow = ks * 16 + ((lm & 1) << 3) + lr;
                uint32_t ncol = wn * 32 + np * 16 + ((lm >> 1) << 3);
                LDSM4T(r0, r1, r2, r3, bs + krow * (LDB * 2) + ncol * 2);
                b[2 * np][0] = r0;     b[2 * np][1] = r1;
                b[2 * np + 1][0] = r2; b[2 * np + 1][1] = r3;
            }
            #pragma unroll
            for (int mf = 0; mf < 4; mf++)
                #pragma unroll
                for (int nf = 0; nf < 4; nf++)
                    mma_f16(acc[mf][nf], a[mf], b[nf]);
        }
        __syncthreads();

        // rotate buffers
        uint32_t ta = sA0; sA0 = sA1; sA1 = sA2; sA2 = ta;
        uint32_t tb = sB0; sB0 = sB1; sB1 = sB2; sB2 = tb;
    }

    const int nbat = n0 >> 14;
    const int pix0 = n0 & 16383;
    #pragma unroll
    for (int mf = 0; mf < 4; mf++) {
        int o = m0 + wm * 64 + mf * 16 + gid;
        #pragma unroll
        for (int nf = 0; nf < 4; nf++) {
            int qoff = pix0 + wn * 32 + nf * 8 + tig * 2;
            float* d0 = out + ((size_t)nbat * CIN + o) * NPIX + qoff;
            *reinterpret_cast<float2*>(d0) = make_float2(acc[mf][nf][0], acc[mf][nf][1]);
            float* d1 = out + ((size_t)nbat * CIN + o + 8) * NPIX + qoff;
            *reinterpret_cast<float2*>(d1) = make_float2(acc[mf][nf][2], acc[mf][nf][3]);
        }
    }
}

// ---------------- launch ----------------
extern "C" void kernel_launch(void* const* d_in, const int* in_sizes, int n_in,
                              void* d_out, int out_size) {
    const float* x   = (const float*)d_in[0];   // [2,256,64,64]
    const float* lat = (const float*)d_in[1];   // [2,128,1,1]
    const float* tw  = (const float*)d_in[2];   // [256,128,3,3]
    const float* w1  = (const float*)d_in[3];   // [64,128,3,3]
    const float* b1  = (const float*)d_in[4];   // [64]
    const float* w2  = (const float*)d_in[5];   // [18,64,3,3]
    const float* b2  = (const float*)d_in[6];   // [18]
    float* out = (float*)d_out;                 // [2,256,128,128]

    cudaFuncSetAttribute(k_gemm, cudaFuncAttributeMaxDynamicSharedMemorySize, GSMEM);

    k_prep<<<2193, 256>>>(tw, x, lat, w1, b1, w2, b2);
    k_tc<<<256, 256>>>();
    k_sample<<<32768, 256>>>();
    k_gemm<<<dim3(256, 2), 256, GSMEM>>>(out);
}

// round 17
// speedup vs baseline: 2.7169x; 1.0518x over previous
#include <cuda_runtime.h>
#include <cuda_fp16.h>
#include <cstdint>
#include <math.h>

#define NB   2
#define CIN  256     // deform output channels O (GEMM M); also transconv input channels
#define CMID 128     // transconv output channels
#define H0   64
#define W0   64
#define H    128
#define W    128
#define KK   9
#define KC   1152    // KK * CMID
#define NPIX 16384
#define QTOT 32768   // GEMM N total
#define KTC  2304    // transconv class-grouped K total (256+512+512+1024)

// ---------------- device scratch ----------------
__device__ float  g_up[NB][CMID][H][W];      // transposed-conv output
__device__ __half g_ST[KC][QTOT];            // im2col, [kc][q] N-contiguous, fp16
__device__ __half g_Wa[CIN][KC];             // deform GEMM A, m-major k-contig, fp16
__device__ __half g_Wc[CMID][KTC];           // transconv GEMM A, class-grouped k
__device__ __half g_xhA[NB * CIN * 65 * 64]; // x fp16, padded (zero row u=64)
__device__ __half g_xhB[NB * CIN * 65 * 64]; // x shifted by +1 in j (zero fill)
__device__ int    g_tiy[NB][KK];
__device__ int    g_tix[NB][KK];
__device__ float  g_twgt[NB][KK][4];

__device__ __forceinline__ uint32_t smem_u32(const void* p) {
    uint32_t a;
    asm("{ .reg .u64 t; cvta.to.shared.u64 t, %1; cvt.u32.u64 %0, t; }" : "=r"(a) : "l"(p));
    return a;
}

#define CP16(sm, gp) \
    asm volatile("cp.async.cg.shared.global [%0], [%1], 16;" :: "r"(sm), "l"(gp) : "memory")
#define CP_COMMIT() asm volatile("cp.async.commit_group;" ::: "memory")
#define CP_WAIT1()  asm volatile("cp.async.wait_group 1;" ::: "memory")
#define CP_WAIT2()  asm volatile("cp.async.wait_group 2;" ::: "memory")
#define CP_WAIT0()  asm volatile("cp.async.wait_group 0;" ::: "memory")

#define LDSM4(R0, R1, R2, R3, a) \
    asm volatile("ldmatrix.sync.aligned.m8n8.x4.shared.b16 {%0,%1,%2,%3}, [%4];" \
                 : "=r"(R0), "=r"(R1), "=r"(R2), "=r"(R3) : "r"(a))
#define LDSM4T(R0, R1, R2, R3, a) \
    asm volatile("ldmatrix.sync.aligned.m8n8.x4.trans.shared.b16 {%0,%1,%2,%3}, [%4];" \
                 : "=r"(R0), "=r"(R1), "=r"(R2), "=r"(R3) : "r"(a))

__device__ __forceinline__ void mma_f16(float* c, const uint32_t* a, const uint32_t* b) {
    asm volatile(
        "mma.sync.aligned.m16n8k16.row.col.f32.f16.f16.f32 "
        "{%0,%1,%2,%3}, {%4,%5,%6,%7}, {%8,%9}, {%0,%1,%2,%3};"
        : "+f"(c[0]), "+f"(c[1]), "+f"(c[2]), "+f"(c[3])
        : "r"(a[0]), "r"(a[1]), "r"(a[2]), "r"(a[3]), "r"(b[0]), "r"(b[1]));
}

// ---------------- merged prep: weights + x fp16 + offset net ----------------
// blocks: [0,1152) weights (coalesced read, scattered write) | [1152,2192) xprep | 2192 offsets
__global__ void k_prep(const float* __restrict__ w, const float* __restrict__ x,
                       const float* __restrict__ lat,
                       const float* __restrict__ w1, const float* __restrict__ b1,
                       const float* __restrict__ w2, const float* __restrict__ b2) {
    __shared__ float sh[NB][64];
    __shared__ float soff[NB][18];
    int b = blockIdx.x;
    int t = threadIdx.x;
    if (b < 1152) {
        int e = b * 256 + t;   // < 294912, coalesced read of w
        float v = w[e];
        __half h = __float2half_rn(v);
        int o = e / KC;                 // CIN index (deform out channel)
        int r = e - o * KC;
        int c = r / KK;                 // CMID index
        int k = r - c * KK;             // tap
        // deform GEMM A: g_Wa[o][k*128 + c]
        g_Wa[o][k * 128 + c] = h;
        // transconv GEMM A: g_Wc[c][pos], class-grouped inverse map
        int ky = k / 3, kx = k - ky * 3;
        int pos;
        if (ky == 1 && kx == 1)      pos = o;
        else if (ky == 1)            pos = 256 + o * 2 + (kx >> 1);
        else if (kx == 1)            pos = 768 + o * 2 + (ky >> 1);
        else                         pos = 1280 + o * 4 + (ky >> 1) * 2 + (kx >> 1);
        g_Wc[c][pos] = h;
    } else if (b < 2192) {
        int idx = (b - 1152) * 256 + t;   // < 266240
        int chunk = idx & 7;
        int row = idx >> 3;                 // (n*256+ci)*65 + u
        int u = row % 65;
        int nc = row / 65;
        int v0 = chunk * 8;
        __align__(16) __half ha[8];
        __align__(16) __half hb[8];
        if (u < 64) {
            const float* src = x + ((size_t)nc * 64 + u) * 64 + v0;
            #pragma unroll
            for (int p = 0; p < 8; p++) ha[p] = __float2half_rn(src[p]);
            #pragma unroll
            for (int p = 0; p < 8; p++) {
                hb[p] = __float2half_rn(0.f);
                if (v0 + p + 1 < 64) hb[p] = __float2half_rn(src[p + 1]);
            }
        } else {
            #pragma unroll
            for (int p = 0; p < 8; p++) { ha[p] = __float2half_rn(0.f); hb[p] = __float2half_rn(0.f); }
        }
        size_t dst = (size_t)row * 64 + v0;
        *reinterpret_cast<uint4*>(&g_xhA[dst]) = *reinterpret_cast<uint4*>(ha);
        *reinterpret_cast<uint4*>(&g_xhB[dst]) = *reinterpret_cast<uint4*>(hb);
    } else {
        // offset net + tap precompute (single block)
        if (t < 128) {
            int n = t >> 6, o = t & 63;
            float acc = b1[o];
            for (int i = 0; i < CMID; i++)
                acc += lat[n * CMID + i] * w1[(o * CMID + i) * KK + 4];
            sh[n][o] = fmaxf(acc, 0.f);
        }
        __syncthreads();
        if (t < NB * 18) {
            int nn = t / 18, j = t % 18;
            float a = b2[j];
            for (int q = 0; q < 64; q++)
                a += sh[nn][q] * w2[(j * 64 + q) * KK + 4];
            soff[nn][j] = tanhf(a);
        }
        __syncthreads();
        if (t < NB * KK) {
            int nn = t / KK, k = t % KK;
            float oy = soff[nn][2 * k], ox = soff[nn][2 * k + 1];
            float ay = (float)(k / 3 - 1) + oy;
            float ax = (float)(k % 3 - 1) + ox;
            float fy = floorf(ay), fx = floorf(ax);
            float dy = ay - fy, dx = ax - fx;
            g_tiy[nn][k] = (int)fy;
            g_tix[nn][k] = (int)fx;
            g_twgt[nn][k][0] = (1.f - dy) * (1.f - dx);
            g_twgt[nn][k][1] = (1.f - dy) * dx;
            g_twgt[nn][k][2] = dy * (1.f - dx);
            g_twgt[nn][k][3] = dy * dx;
        }
    }
}

// ---------------- kernel B: transposed conv as 4 parity-class HMMA GEMMs ----------------
// heavy classes first: cls = 3 - (bx>>6)
#define TLDA 40
#define TLDB 136
__global__ __launch_bounds__(256, 2) void k_tc() {
    __shared__ __half As[2][128][TLDA];
    __shared__ __half Bs[2][32][TLDB];

    const int bx = blockIdx.x;
    const int cls = 3 - (bx >> 6), cb = bx & 63;
    const int ry = cls >> 1, rx = cls & 1;
    const int sh = ry + rx, nt = 1 << sh;
    const int n = cb >> 5, u0 = (cb & 31) << 1;
    const int koff = (cls == 0) ? 0 : (cls == 1) ? 256 : (cls == 2) ? 768 : 1280;
    const int nkt = 8 << sh;

    const int t = threadIdx.x, wid = t >> 5, lane = t & 31;
    const int gid = lane >> 2, tig = lane & 3, lr = lane & 7, lm = lane >> 3;
    const int wm = wid >> 2, wn = wid & 3;

    const uint32_t asb = smem_u32(&As[0][0][0]);
    const uint32_t bsb = smem_u32(&Bs[0][0][0]);
    const __half* Wc = &g_Wc[0][0];

    float acc[4][4][4];
    #pragma unroll
    for (int i = 0; i < 4; i++)
        #pragma unroll
        for (int j = 0; j < 4; j++)
            #pragma unroll
            for (int c = 0; c < 4; c++) acc[i][j][c] = 0.f;

    auto stage = [&](int buf, int k0) {
        #pragma unroll
        for (int h = 0; h < 2; h++) {
            int c = t + h * 256;
            int row = c >> 2, u4 = c & 3;
            CP16(asb + buf * (128 * TLDA * 2) + row * (TLDA * 2) + u4 * 16,
                 Wc + (size_t)row * KTC + koff + k0 + u4 * 8);
        }
        #pragma unroll
        for (int h = 0; h < 2; h++) {
            int c = t + h * 256;
            int row = c >> 4, rest = c & 15;
            int du = rest >> 3, vv = (rest & 7) * 8;
            int k = k0 + row;
            int ci = k >> sh, tt = k & (nt - 1);
            int ty = tt >> rx, tx = tt & rx;
            int iof = ry & (ty ^ 1);
            int jof = rx & (tx ^ 1);
            const __half* src = jof ? g_xhB : g_xhA;
            size_t ga = ((size_t)(n * CIN + ci) * 65 + (u0 + du + iof)) * 64 + vv;
            CP16(bsb + buf * (32 * TLDB * 2) + row * (TLDB * 2) + (du * 64 + vv) * 2,
                 src + ga);
        }
    };

    stage(0, 0);
    CP_COMMIT();

    for (int kt = 0; kt < nkt; kt++) {
        const int cur = kt & 1;
        if (kt + 1 < nkt) {
            stage(cur ^ 1, (kt + 1) * 32);
            CP_COMMIT();
            CP_WAIT1();
        } else {
            CP_WAIT0();
        }
        __syncthreads();

        const uint32_t as = asb + cur * (128 * TLDA * 2);
        const uint32_t bs = bsb + cur * (32 * TLDB * 2);

        #pragma unroll
        for (int ks = 0; ks < 2; ks++) {
            uint32_t a[4][4], b[4][2];
            #pragma unroll
            for (int mf = 0; mf < 4; mf++) {
                uint32_t row = wm * 64 + mf * 16 + ((lm & 1) << 3) + lr;
                uint32_t colb = ks * 32 + ((lm >> 1) << 4);
                LDSM4(a[mf][0], a[mf][1], a[mf][2], a[mf][3],
                      as + row * (TLDA * 2) + colb);
            }
            #pragma unroll
            for (int np = 0; np < 2; np++) {
                uint32_t r0, r1, r2, r3;
                uint32_t krow = ks * 16 + ((lm & 1) << 3) + lr;
                uint32_t ncol = wn * 32 + np * 16 + ((lm >> 1) << 3);
                LDSM4T(r0, r1, r2, r3, bs + krow * (TLDB * 2) + ncol * 2);
                b[2 * np][0] = r0;     b[2 * np][1] = r1;
                b[2 * np + 1][0] = r2; b[2 * np + 1][1] = r3;
            }
            #pragma unroll
            for (int mf = 0; mf < 4; mf++)
                #pragma unroll
                for (int nf = 0; nf < 4; nf++)
                    mma_f16(acc[mf][nf], a[mf], b[nf]);
        }
        __syncthreads();
    }

    #pragma unroll
    for (int mf = 0; mf < 4; mf++) {
        int m = wm * 64 + mf * 16 + gid;
        #pragma unroll
        for (int nf = 0; nf < 4; nf++) {
            int nn = wn * 32 + nf * 8 + tig * 2;
            int du = nn >> 6, v = nn & 63;
            int Y = 2 * (u0 + du) + ry;
            int X = 2 * v + rx;
            g_up[n][m][Y][X]         = acc[mf][nf][0];
            g_up[n][m][Y][X + 2]     = acc[mf][nf][1];
            g_up[n][m + 8][Y][X]     = acc[mf][nf][2];
            g_up[n][m + 8][Y][X + 2] = acc[mf][nf][3];
        }
    }
}

// ---------------- kernel C1: smem-staged bilinear gather, 4 y-rows per block ----------------
// block = (n, c, y0=4*yb): stage rows y0-2..y0+5 (cols -2..129), compute 9 taps x 4 rows x 128 x.
__global__ __launch_bounds__(256) void k_sample() {
    __shared__ float s[8][132];
    __shared__ int   stiy[KK];
    __shared__ int   stix[KK];
    __shared__ float swt[KK][4];

    const int bx = blockIdx.x;        // n*4096 + c*32 + yb
    const int yb = bx & 31;
    const int c  = (bx >> 5) & 127;
    const int n  = bx >> 12;
    const int y0 = yb << 2;
    const int t  = threadIdx.x;

    if (t < KK) {
        stiy[t] = g_tiy[n][t];
        stix[t] = g_tix[n][t];
        swt[t][0] = g_twgt[n][t][0];
        swt[t][1] = g_twgt[n][t][1];
        swt[t][2] = g_twgt[n][t][2];
        swt[t][3] = g_twgt[n][t][3];
    }

    // stage 8 rows x 132 cols (row r = y0-2+j, col cc = -2..129), zero out-of-range
    const float* U = &g_up[n][c][0][0];
    #pragma unroll
    for (int it = 0; it < 5; it++) {
        int e = t + it * 256;
        if (e < 1056) {
            int j  = e / 132;
            int ei = e - j * 132;
            int r  = y0 - 2 + j;
            int cc = ei - 2;
            float v = 0.f;
            if (r >= 0 && r < H && cc >= 0 && cc < W) v = U[r * W + cc];
            s[j][ei] = v;
        }
    }
    __syncthreads();

    // 4 rows x 9 taps x 64 x-pairs = 2304 half2 outputs, 9 per thread
    __half* STbase = &g_ST[c][(n << 14) + (y0 << 7)];
    #pragma unroll
    for (int it = 0; it < 9; it++) {
        int e = t + it * 256;          // < 2304
        int dy = e / 576;
        int rm = e - dy * 576;
        int k  = rm >> 6;              // 0..8
        int xp = rm & 63;
        int x  = xp << 1;
        int j0 = dy + stiy[k] + 2;     // 0..7
        int xi = x + stix[k] + 2;      // 0..130
        float w00 = swt[k][0], w01 = swt[k][1], w10 = swt[k][2], w11 = swt[k][3];
        float a0 = s[j0][xi], a1 = s[j0][xi + 1], a2 = s[j0][xi + 2];
        float b0 = s[j0 + 1][xi], b1 = s[j0 + 1][xi + 1], b2 = s[j0 + 1][xi + 2];
        __half2 h;
        h.x = __float2half_rn(w00 * a0 + w01 * a1 + w10 * b0 + w11 * b1);
        h.y = __float2half_rn(w00 * a1 + w01 * a2 + w10 * b1 + w11 * b2);
        *reinterpret_cast<__half2*>(STbase + (size_t)k * 128 * QTOT + (dy << 7) + x) = h;
    }
}

// ---------------- kernel C2: fp16 HMMA GEMM, 3-stage pipeline, 128x128 tiles ----------------
#define BK      32
#define NTILE   36            // 1152 / 32
#define LDH     40
#define LDB     136
#define ASTG    (128 * LDH * 2)   // 10240 B per A stage
#define BSTG    (32 * LDB * 2)    // 8704 B per B stage
#define GSMEM   (3 * (ASTG + BSTG))  // 56832 B

__global__ __launch_bounds__(256, 2) void k_gemm(float* __restrict__ out) {
    extern __shared__ char dsm[];

    const int nb = blockIdx.x;           // 256 N-blocks of 128 q
    const int mb = blockIdx.y;           // 2 M-blocks of 128 o
    const int t  = threadIdx.x;
    const int wid = t >> 5, lane = t & 31;
    const int gid = lane >> 2, tig = lane & 3;
    const int lr = lane & 7, lm = lane >> 3;
    const int wm = wid >> 2, wn = wid & 3;
    const int m0 = mb * 128, n0 = nb * 128;

    const uint32_t smb = smem_u32(dsm);
    uint32_t sA0 = smb,              sB0 = smb + 3 * ASTG;
    uint32_t sA1 = smb + ASTG,       sB1 = sB0 + BSTG;
    uint32_t sA2 = smb + 2 * ASTG,   sB2 = sB0 + 2 * BSTG;

    const __half* Ab = &g_Wa[m0][0];
    const __half* Bg = &g_ST[0][0];

    float acc[4][4][4];
    #pragma unroll
    for (int i = 0; i < 4; i++)
        #pragma unroll
        for (int j = 0; j < 4; j++)
            #pragma unroll
            for (int c = 0; c < 4; c++) acc[i][j][c] = 0.f;

    auto stage = [&](uint32_t ab, uint32_t bb, int k0) {
        // A: 128 rows x 32 k = 512 x 16B
        #pragma unroll
        for (int h = 0; h < 2; h++) {
            int c = t + h * 256;
            int row = c >> 2, u4 = c & 3;
            CP16(ab + row * (LDH * 2) + u4 * 16, Ab + (size_t)row * KC + k0 + u4 * 8);
        }
        // B: 32 k-rows x 128 q = 512 x 16B
        #pragma unroll
        for (int h = 0; h < 2; h++) {
            int c = t + h * 256;
            int row = c >> 4, vv = (c & 15) * 8;
            CP16(bb + row * (LDB * 2) + vv * 2, Bg + (size_t)(k0 + row) * QTOT + n0 + vv);
        }
    };

    stage(sA0, sB0, 0);
    CP_COMMIT();
    stage(sA1, sB1, BK);
    CP_COMMIT();

    for (int kt = 0; kt < NTILE; kt++) {
        if (kt + 2 < NTILE) stage(sA2, sB2, (kt + 2) * BK);
        CP_COMMIT();
        CP_WAIT2();
        __syncthreads();

        const uint32_t as = sA0, bs = sB0;

        #pragma unroll
        for (int ks = 0; ks < 2; ks++) {
            uint32_t a[4][4], b[4][2];
            #pragma unroll
            for (int mf = 0; mf < 4; mf++) {
                uint32_t row = wm * 64 + mf * 16 + ((lm & 1) << 3) + lr;
                uint32_t colb = ks * 32 + ((lm >> 1) << 4);
                LDSM4(a[mf][0], a[mf][1], a[mf][2], a[mf][3],
                      as + row * (LDH * 2) + colb);
            }
            #pragma unroll
            for (int np = 0; np < 2; np++) {
                uint32_t r0, r1, r2, r3;
                uint32_t krow = ks * 16 + ((lm & 1) << 3) + lr;
                uint32_t ncol = wn * 32 + np * 16 + ((lm >> 1) << 3);
                LDSM4T(r0, r1, r2, r3, bs + krow * (LDB * 2) + ncol * 2);
                b[2 * np][0] = r0;     b[2 * np][1] = r1;
                b[2 * np + 1][0] = r2; b[2 * np + 1][1] = r3;
            }
            #pragma unroll
            for (int mf = 0; mf < 4; mf++)
                #pragma unroll
                for (int nf = 0; nf < 4; nf++)
                    mma_f16(acc[mf][nf], a[mf], b[nf]);
        }
        __syncthreads();

        // rotate buffers
        uint32_t ta = sA0; sA0 = sA1; sA1 = sA2; sA2 = ta;
        uint32_t tb = sB0; sB0 = sB1; sB1 = sB2; sB2 = tb;
    }

    const int nbat = n0 >> 14;
    const int pix0 = n0 & 16383;
    #pragma unroll
    for (int mf = 0; mf < 4; mf++) {
        int o = m0 + wm * 64 + mf * 16 + gid;
        #pragma unroll
        for (int nf = 0; nf < 4; nf++) {
            int qoff = pix0 + wn * 32 + nf * 8 + tig * 2;
            float* d0 = out + ((size_t)nbat * CIN + o) * NPIX + qoff;
            *reinterpret_cast<float2*>(d0) = make_float2(acc[mf][nf][0], acc[mf][nf][1]);
            float* d1 = out + ((size_t)nbat * CIN + o + 8) * NPIX + qoff;
            *reinterpret_cast<float2*>(d1) = make_float2(acc[mf][nf][2], acc[mf][nf][3]);
        }
    }
}

// ---------------- launch ----------------
extern "C" void kernel_launch(void* const* d_in, const int* in_sizes, int n_in,
                              void* d_out, int out_size) {
    const float* x   = (const float*)d_in[0];   // [2,256,64,64]
    const float* lat = (const float*)d_in[1];   // [2,128,1,1]
    const float* tw  = (const float*)d_in[2];   // [256,128,3,3]
    const float* w1  = (const float*)d_in[3];   // [64,128,3,3]
    const float* b1  = (const float*)d_in[4];   // [64]
    const float* w2  = (const float*)d_in[5];   // [18,64,3,3]
    const float* b2  = (const float*)d_in[6];   // [18]
    float* out = (float*)d_out;                 // [2,256,128,128]

    cudaFuncSetAttribute(k_gemm, cudaFuncAttributeMaxDynamicSharedMemorySize, GSMEM);

    k_prep<<<2193, 256>>>(tw, x, lat, w1, b1, w2, b2);
    k_tc<<<256, 256>>>();
    k_sample<<<8192, 256>>>();
    k_gemm<<<dim3(256, 2), 256, GSMEM>>>(out);
}